// round 15
// baseline (speedup 1.0000x reference)
#include <cuda_runtime.h>
#include <math.h>
#include <stdint.h>

#define NN    10000
#define EEMAX 320000
#define ETOTM (EEMAX + NN)

// ---------------- scratch: double-buffered per branch ----------------
__device__ __align__(16) float g_h1[2 * NN * 384];
__device__ __align__(16) float g_s1[2 * NN * 3];
__device__ __align__(16) float g_d1[2 * NN * 3];
__device__ __align__(16) float g_rden1[2 * NN * 3];   // 1/den per (dst, head)
__device__ __align__(16) float g_agg1[2 * NN * 384];
__device__ __align__(16) float g_h2[2 * NN * 128];
__device__ __align__(16) float g_s2[2 * NN];
__device__ __align__(16) float g_d2[2 * NN];
__device__ __align__(16) float g_exp1[2 * 3 * ETOTM];
__device__ __align__(16) float g_exp2[2 * ETOTM];
__device__ __align__(16) float g_agg2[2 * NN * 128];
__device__ __align__(16) float g_pool[2 * 256];
// CSR per branch
__device__ int g_deg[2 * NN];
__device__ int g_off[2 * (NN + 1)];
__device__ int g_fill[2 * NN];
__device__ int g_esrc[2 * ETOTM];

// ---------------- CSR build ----------------
__global__ void init_deg(int Ncnt)
{
    int i = blockIdx.x * blockDim.x + threadIdx.x;
    if (i < 2 * Ncnt) g_deg[i] = 0;
}

__global__ void csr_count(const int* __restrict__ ei1, const int* __restrict__ ei2,
                          int E, int Ncnt)
{
    int t = blockIdx.x * blockDim.x + threadIdx.x;
    int Etot = E + Ncnt;
    if (t >= 2 * Etot) return;
    int b = (t >= Etot) ? 1 : 0;
    int e = t - b * Etot;
    const int* ei = b ? ei2 : ei1;
    int dst = (e < E) ? ei[E + e] : (e - E);
    dst = min(max(dst, 0), Ncnt - 1);
    atomicAdd(&g_deg[b * NN + dst], 1);
}

__global__ void csr_scan(int Ncnt, int Etot)
{
    __shared__ int part[1024];
    int b = blockIdx.x;
    int* deg = g_deg + b * NN;
    int* off = g_off + b * (NN + 1);
    int* fil = g_fill + b * NN;
    int t = threadIdx.x;
    int chunk = (Ncnt + 1023) / 1024;
    int s0 = t * chunk;
    int s1 = min(s0 + chunk, Ncnt);
    int s = 0;
    for (int i = s0; i < s1; i++) s += deg[i];
    part[t] = s;
    __syncthreads();
    for (int o = 1; o < 1024; o <<= 1) {
        int v = (t >= o) ? part[t - o] : 0;
        __syncthreads();
        part[t] += v;
        __syncthreads();
    }
    int run = part[t] - s;
    for (int i = s0; i < s1; i++) {
        off[i] = run;
        fil[i] = run;
        run += deg[i];
    }
    if (t == 0) off[Ncnt] = Etot;
}

__global__ void csr_scatter(const int* __restrict__ ei1, const int* __restrict__ ei2,
                            int E, int Ncnt)
{
    int t = blockIdx.x * blockDim.x + threadIdx.x;
    int Etot = E + Ncnt;
    if (t >= 2 * Etot) return;
    int b = (t >= Etot) ? 1 : 0;
    int e = t - b * Etot;
    const int* ei = b ? ei2 : ei1;
    int src, dst;
    if (e < E) { src = ei[e]; dst = ei[E + e]; }
    else       { src = e - E; dst = src; }
    src = min(max(src, 0), Ncnt - 1);
    dst = min(max(dst, 0), Ncnt - 1);
    int pos = atomicAdd(&g_fill[b * NN + dst], 1);
    g_esrc[b * ETOTM + pos] = src;
}

// ---------------- GEMM1: h1[b][M,384] = x_b[M,256] @ W1[256,384] ----------------
__global__ __launch_bounds__(256) void gemm_l1(const float* __restrict__ A1,
                                               const float* __restrict__ A2,
                                               const float* __restrict__ B, int M)
{
    const int N = 384, K = 256;
    __shared__ float As[16][132];
    __shared__ float Bs[16][128];
    const int tid = threadIdx.x;
    const int tx = tid & 15, ty = tid >> 4;
    const int row0 = blockIdx.y * 128, col0 = blockIdx.x * 128;
    const float* A = blockIdx.z ? A2 : A1;
    float* H = g_h1 + (size_t)blockIdx.z * NN * 384;
    float acc[8][8] = {};

    const int ar = tid >> 1, ac = (tid & 1) * 8;
    const int br = tid >> 4, bc = (tid & 15) * 8;
    const int arow = row0 + ar;

    for (int k0 = 0; k0 < K; k0 += 16) {
        {
            float4 a0 = make_float4(0.f, 0.f, 0.f, 0.f), a1 = a0;
            if (arow < M) {
                a0 = *(const float4*)(A + (size_t)arow * K + k0 + ac);
                a1 = *(const float4*)(A + (size_t)arow * K + k0 + ac + 4);
            }
            As[ac + 0][ar] = a0.x; As[ac + 1][ar] = a0.y;
            As[ac + 2][ar] = a0.z; As[ac + 3][ar] = a0.w;
            As[ac + 4][ar] = a1.x; As[ac + 5][ar] = a1.y;
            As[ac + 6][ar] = a1.z; As[ac + 7][ar] = a1.w;

            *(float4*)&Bs[br][bc]     = *(const float4*)(B + (size_t)(k0 + br) * N + col0 + bc);
            *(float4*)&Bs[br][bc + 4] = *(const float4*)(B + (size_t)(k0 + br) * N + col0 + bc + 4);
        }
        __syncthreads();

        #pragma unroll
        for (int k = 0; k < 16; k++) {
            float a[8], b[8];
            #pragma unroll
            for (int i = 0; i < 8; i++) a[i] = As[k][ty * 8 + i];
            #pragma unroll
            for (int j = 0; j < 8; j++) b[j] = Bs[k][tx * 8 + j];
            #pragma unroll
            for (int i = 0; i < 8; i++)
                #pragma unroll
                for (int j = 0; j < 8; j++)
                    acc[i][j] += a[i] * b[j];
        }
        __syncthreads();
    }
    #pragma unroll
    for (int i = 0; i < 8; i++) {
        int row = row0 + ty * 8 + i;
        if (row < M) {
            *(float4*)(H + (size_t)row * N + col0 + tx * 8) =
                make_float4(acc[i][0], acc[i][1], acc[i][2], acc[i][3]);
            *(float4*)(H + (size_t)row * N + col0 + tx * 8 + 4) =
                make_float4(acc[i][4], acc[i][5], acc[i][6], acc[i][7]);
        }
    }
}

// ---------------- GEMM2: h2[b][M,128] = relu(agg1[b]+b1)[M,384] @ W2 ----------
__global__ __launch_bounds__(256) void gemm_l2(const float* __restrict__ B,
                                               const float* __restrict__ abias, int M)
{
    const int N = 128, K = 384;
    __shared__ float As[16][132];
    __shared__ float Bs[16][64];
    const int tid = threadIdx.x;
    const int tx = tid & 15, ty = tid >> 4;
    const int row0 = blockIdx.y * 128, col0 = blockIdx.x * 64;
    const float* AG = g_agg1 + (size_t)blockIdx.z * NN * 384;
    float* H = g_h2 + (size_t)blockIdx.z * NN * 128;
    float acc[8][4] = {};

    const int ar = tid >> 1, ac = (tid & 1) * 8;
    const int arow = row0 + ar;
    const int br = tid >> 4, bc = (tid & 15) * 4;

    for (int k0 = 0; k0 < K; k0 += 16) {
        {
            float4 a0 = make_float4(0.f, 0.f, 0.f, 0.f), a1 = a0;
            if (arow < M) {
                a0 = *(const float4*)(AG + (size_t)arow * K + k0 + ac);
                a1 = *(const float4*)(AG + (size_t)arow * K + k0 + ac + 4);
                a0.x = fmaxf(a0.x + abias[k0 + ac + 0], 0.f);
                a0.y = fmaxf(a0.y + abias[k0 + ac + 1], 0.f);
                a0.z = fmaxf(a0.z + abias[k0 + ac + 2], 0.f);
                a0.w = fmaxf(a0.w + abias[k0 + ac + 3], 0.f);
                a1.x = fmaxf(a1.x + abias[k0 + ac + 4], 0.f);
                a1.y = fmaxf(a1.y + abias[k0 + ac + 5], 0.f);
                a1.z = fmaxf(a1.z + abias[k0 + ac + 6], 0.f);
                a1.w = fmaxf(a1.w + abias[k0 + ac + 7], 0.f);
            }
            As[ac + 0][ar] = a0.x; As[ac + 1][ar] = a0.y;
            As[ac + 2][ar] = a0.z; As[ac + 3][ar] = a0.w;
            As[ac + 4][ar] = a1.x; As[ac + 5][ar] = a1.y;
            As[ac + 6][ar] = a1.z; As[ac + 7][ar] = a1.w;

            *(float4*)&Bs[br][bc] = *(const float4*)(B + (size_t)(k0 + br) * N + col0 + bc);
        }
        __syncthreads();

        #pragma unroll
        for (int k = 0; k < 16; k++) {
            float a[8], b[4];
            #pragma unroll
            for (int i = 0; i < 8; i++) a[i] = As[k][ty * 8 + i];
            #pragma unroll
            for (int j = 0; j < 4; j++) b[j] = Bs[k][tx * 4 + j];
            #pragma unroll
            for (int i = 0; i < 8; i++)
                #pragma unroll
                for (int j = 0; j < 4; j++)
                    acc[i][j] += a[i] * b[j];
        }
        __syncthreads();
    }
    #pragma unroll
    for (int i = 0; i < 8; i++) {
        int row = row0 + ty * 8 + i;
        if (row < M)
            *(float4*)(H + (size_t)row * N + col0 + tx * 4) =
                make_float4(acc[i][0], acc[i][1], acc[i][2], acc[i][3]);
    }
}

// ---------------- s/d (both branches): warp per (b, node, head) ---------------
__global__ void sd_l1(const float* __restrict__ asrc, const float* __restrict__ adst, int n)
{
    int w = (blockIdx.x * blockDim.x + threadIdx.x) >> 5;
    int lane = threadIdx.x & 31;
    if (w >= 2 * n * 3) return;
    int b = w / (n * 3);
    int loc = w - b * n * 3;
    int hd = loc % 3;
    float4 hv = *(const float4*)(g_h1 + ((size_t)b * NN * 3 + loc) * 128 + lane * 4);
    float4 sa = *(const float4*)(asrc + hd * 128 + lane * 4);
    float4 da = *(const float4*)(adst + hd * 128 + lane * 4);
    float ss = hv.x * sa.x + hv.y * sa.y + hv.z * sa.z + hv.w * sa.w;
    float dd = hv.x * da.x + hv.y * da.y + hv.z * da.z + hv.w * da.w;
    #pragma unroll
    for (int o = 16; o; o >>= 1) {
        ss += __shfl_down_sync(0xffffffffu, ss, o);
        dd += __shfl_down_sync(0xffffffffu, dd, o);
    }
    if (lane == 0) { g_s1[b * NN * 3 + loc] = ss; g_d1[b * NN * 3 + loc] = dd; }
}

__global__ void sd_l2(const float* __restrict__ asrc, const float* __restrict__ adst, int n)
{
    int w = (blockIdx.x * blockDim.x + threadIdx.x) >> 5;
    int lane = threadIdx.x & 31;
    if (w >= 2 * n) return;
    int b = w / n;
    int loc = w - b * n;
    float4 hv = *(const float4*)(g_h2 + ((size_t)b * NN + loc) * 128 + lane * 4);
    float4 sa = *(const float4*)(asrc + lane * 4);
    float4 da = *(const float4*)(adst + lane * 4);
    float ss = hv.x * sa.x + hv.y * sa.y + hv.z * sa.z + hv.w * sa.w;
    float dd = hv.x * da.x + hv.y * da.y + hv.z * da.z + hv.w * da.w;
    #pragma unroll
    for (int o = 16; o; o >>= 1) {
        ss += __shfl_down_sync(0xffffffffu, ss, o);
        dd += __shfl_down_sync(0xffffffffu, dd, o);
    }
    if (lane == 0) { g_s2[b * NN + loc] = ss; g_d2[b * NN + loc] = dd; }
}

// ---------------- layer-1 softmax + aggregation (no output writes) -----------
__global__ __launch_bounds__(256) void agg_l1_csr(int E, int Ncnt)
{
    int b = blockIdx.y;
    int dst = (blockIdx.x * blockDim.x + threadIdx.x) >> 5;
    int lane = threadIdx.x & 31;
    if (dst >= Ncnt) return;
    const int* off  = g_off + b * (NN + 1);
    const int* srcv = g_esrc + b * ETOTM;
    const float* s1 = g_s1 + b * NN * 3;
    float* e0p = g_exp1 + (size_t)(b * 3 + 0) * ETOTM;
    float* e1p = g_exp1 + (size_t)(b * 3 + 1) * ETOTM;
    float* e2p = g_exp1 + (size_t)(b * 3 + 2) * ETOTM;

    int beg = off[dst], end = off[dst + 1];
    float dv0 = g_d1[b * NN * 3 + dst * 3 + 0];
    float dv1 = g_d1[b * NN * 3 + dst * 3 + 1];
    float dv2 = g_d1[b * NN * 3 + dst * 3 + 2];

    // pass A: exp into coalesced scratch + den
    float den0 = 0.f, den1 = 0.f, den2 = 0.f;
    for (int i = beg + lane; i < end; i += 32) {
        int src = srcv[i];
        float e0 = s1[src * 3 + 0] + dv0;
        float e1 = s1[src * 3 + 1] + dv1;
        float e2 = s1[src * 3 + 2] + dv2;
        e0 = e0 > 0.f ? e0 : 0.2f * e0;
        e1 = e1 > 0.f ? e1 : 0.2f * e1;
        e2 = e2 > 0.f ? e2 : 0.2f * e2;
        float x0 = expf(e0), x1 = expf(e1), x2 = expf(e2);
        e0p[i] = x0; e1p[i] = x1; e2p[i] = x2;
        den0 += x0; den1 += x1; den2 += x2;
    }
    #pragma unroll
    for (int o = 16; o; o >>= 1) {
        den0 += __shfl_xor_sync(0xffffffffu, den0, o);
        den1 += __shfl_xor_sync(0xffffffffu, den1, o);
        den2 += __shfl_xor_sync(0xffffffffu, den2, o);
    }
    float r0 = 1.f / den0, r1 = 1.f / den1, r2 = 1.f / den2;
    if (lane == 0) {
        g_rden1[b * NN * 3 + dst * 3 + 0] = r0;
        g_rden1[b * NN * 3 + dst * 3 + 1] = r1;
        g_rden1[b * NN * 3 + dst * 3 + 2] = r2;
    }
    __syncwarp();

    // pass B: gather h1[src] and accumulate
    float acc[12];
    #pragma unroll
    for (int k = 0; k < 12; k++) acc[k] = 0.f;
    const float4* h1b = (const float4*)(g_h1 + (size_t)b * NN * 384);

    #pragma unroll 2
    for (int i = beg; i < end; i++) {
        float a0 = e0p[i] * r0, a1 = e1p[i] * r1, a2 = e2p[i] * r2;
        int src = srcv[i];
        const float4* hs = h1b + (size_t)src * 96;
        float4 v0 = hs[lane];
        float4 v1 = hs[32 + lane];
        float4 v2 = hs[64 + lane];
        acc[0] += v0.x * a0; acc[1]  += v0.y * a0; acc[2]  += v0.z * a0; acc[3]  += v0.w * a0;
        acc[4] += v1.x * a1; acc[5]  += v1.y * a1; acc[6]  += v1.z * a1; acc[7]  += v1.w * a1;
        acc[8] += v2.x * a2; acc[9]  += v2.y * a2; acc[10] += v2.z * a2; acc[11] += v2.w * a2;
    }

    float4* og = (float4*)(g_agg1 + ((size_t)b * NN + dst) * 384);
    og[lane]      = make_float4(acc[0], acc[1], acc[2], acc[3]);
    og[32 + lane] = make_float4(acc[4], acc[5], acc[6], acc[7]);
    og[64 + lane] = make_float4(acc[8], acc[9], acc[10], acc[11]);
}

// ---------------- alpha output: edge-parallel, coalesced, original order ------
__global__ void alpha_l1(const int* __restrict__ ei1, const int* __restrict__ ei2,
                         int E, int Ncnt, float* __restrict__ out, long long out_size)
{
    int t = blockIdx.x * blockDim.x + threadIdx.x;
    int Etot = E + Ncnt;
    if (t >= 2 * Etot) return;
    int b = (t >= Etot) ? 1 : 0;
    int e = t - b * Etot;
    const int* ei = b ? ei2 : ei1;
    int src, dst;
    if (e < E) { src = ei[e]; dst = ei[E + e]; }
    else       { src = e - E; dst = src; }
    src = min(max(src, 0), Ncnt - 1);
    dst = min(max(dst, 0), Ncnt - 1);

    const float* s1 = g_s1 + b * NN * 3;
    const float* d1 = g_d1 + b * NN * 3;
    const float* rd = g_rden1 + b * NN * 3;
    long long ob = 1 + (long long)b * Etot * 3 + 3LL * e;
    if (ob + 2 >= out_size) return;

    #pragma unroll
    for (int h = 0; h < 3; h++) {
        float v = s1[src * 3 + h] + d1[dst * 3 + h];
        v = v > 0.f ? v : 0.2f * v;
        out[ob + h] = expf(v) * rd[dst * 3 + h];
    }
}

// ---------------- layer-2 softmax + aggregation ----------------
__global__ __launch_bounds__(256) void agg_l2_csr(int E, int Ncnt)
{
    int b = blockIdx.y;
    int dst = (blockIdx.x * blockDim.x + threadIdx.x) >> 5;
    int lane = threadIdx.x & 31;
    if (dst >= Ncnt) return;
    const int* off  = g_off + b * (NN + 1);
    const int* srcv = g_esrc + b * ETOTM;
    const float* s2 = g_s2 + b * NN;
    float* xp = g_exp2 + (size_t)b * ETOTM;

    int beg = off[dst], end = off[dst + 1];
    float dv = g_d2[b * NN + dst];
    float den = 0.f;
    for (int i = beg + lane; i < end; i += 32) {
        int src = srcv[i];
        float e = s2[src] + dv;
        e = e > 0.f ? e : 0.2f * e;
        float x = expf(e);
        xp[i] = x;
        den += x;
    }
    #pragma unroll
    for (int o = 16; o; o >>= 1) den += __shfl_xor_sync(0xffffffffu, den, o);
    float r = 1.f / den;
    __syncwarp();

    float4 acc = make_float4(0.f, 0.f, 0.f, 0.f);
    const float4* h2b = (const float4*)(g_h2 + (size_t)b * NN * 128);
    #pragma unroll 2
    for (int i = beg; i < end; i++) {
        float a = xp[i] * r;
        int src = srcv[i];
        float4 v = h2b[(size_t)src * 32 + lane];
        acc.x += v.x * a; acc.y += v.y * a; acc.z += v.z * a; acc.w += v.w * a;
    }
    ((float4*)(g_agg2 + ((size_t)b * NN + dst) * 128))[lane] = acc;
}

// ---------------- pooling: node_attn == 1 identically, so both halves equal ---
__global__ void pool_kernel(const float* __restrict__ b2, int Ncnt)
{
    int c = blockIdx.x;
    int b = blockIdx.y;
    const float* ag = g_agg2 + (size_t)b * NN * 128;
    float bias = b2[c];
    float se = 0.f;
    for (int n = threadIdx.x; n < Ncnt; n += blockDim.x)
        se += ag[(size_t)n * 128 + c] + bias;
    __shared__ float r1[256];
    r1[threadIdx.x] = se;
    __syncthreads();
    for (int o = 128; o; o >>= 1) {
        if (threadIdx.x < o) r1[threadIdx.x] += r1[threadIdx.x + o];
        __syncthreads();
    }
    if (threadIdx.x == 0) {
        float m = r1[0] / (float)Ncnt;
        g_pool[b * 256 + c]       = m;   // weighted.mean == e2.mean (node_attn == 1)
        g_pool[b * 256 + 128 + c] = m;
    }
}

// ---------------- cosine similarity ----------------
__global__ void sim_kernel(float* __restrict__ out, long long out_size)
{
    int t = threadIdx.x;
    float a = g_pool[t], b = g_pool[256 + t];
    __shared__ float sd_[256], sa[256], sb[256];
    sd_[t] = a * b; sa[t] = a * a; sb[t] = b * b;
    __syncthreads();
    for (int o = 128; o; o >>= 1) {
        if (t < o) { sd_[t] += sd_[t + o]; sa[t] += sa[t + o]; sb[t] += sb[t + o]; }
        __syncthreads();
    }
    if (t == 0 && out_size >= 1) {
        float n1 = fmaxf(sqrtf(sa[0]), 1e-8f);
        float n2 = fmaxf(sqrtf(sb[0]), 1e-8f);
        out[0] = sd_[0] / (n1 * n2);
    }
}

// ---------------- host launcher: single stream ----------------
extern "C" void kernel_launch(void* const* d_in, const int* in_sizes, int n_in,
                              void* d_out, int out_size)
{
    const float* x1  = (const float*)d_in[0];
    const int*   ei1 = (const int*)d_in[1];     // int32
    const float* x2  = (const float*)d_in[2];
    const int*   ei2 = (const int*)d_in[3];
    const float* W1  = (const float*)d_in[4];
    const float* as1 = (const float*)d_in[5];
    const float* ad1 = (const float*)d_in[6];
    const float* b1  = (const float*)d_in[7];
    const float* W2  = (const float*)d_in[8];
    const float* as2 = (const float*)d_in[9];
    const float* ad2 = (const float*)d_in[10];
    const float* b2  = (const float*)d_in[11];
    float* out = (float*)d_out;
    const long long osz = (long long)out_size;

    const int Ncnt = in_sizes[0] / 256;
    const int E    = in_sizes[1] / 2;
    const int Etot = E + Ncnt;

    const int e2blocks = (2 * Etot + 255) / 256;
    const int nwb = (Ncnt * 32 + 255) / 256;

    // CSR build, both branches fused
    init_deg<<<(2 * Ncnt + 255) / 256, 256>>>(Ncnt);
    csr_count<<<e2blocks, 256>>>(ei1, ei2, E, Ncnt);
    csr_scan<<<2, 1024>>>(Ncnt, Etot);
    csr_scatter<<<e2blocks, 256>>>(ei1, ei2, E, Ncnt);

    // layer 1 (both branches)
    gemm_l1<<<dim3(3, (Ncnt + 127) / 128, 2), 256>>>(x1, x2, W1, Ncnt);
    sd_l1<<<(2 * Ncnt * 3 * 32 + 255) / 256, 256>>>(as1, ad1, Ncnt);
    agg_l1_csr<<<dim3(nwb, 2), 256>>>(E, Ncnt);
    alpha_l1<<<e2blocks, 256>>>(ei1, ei2, E, Ncnt, out, osz);

    // layer 2 (both branches)
    gemm_l2<<<dim3(2, (Ncnt + 127) / 128, 2), 256>>>(W2, b1, Ncnt);
    sd_l2<<<(2 * Ncnt * 32 + 255) / 256, 256>>>(as2, ad2, Ncnt);
    agg_l2_csr<<<dim3(nwb, 2), 256>>>(E, Ncnt);

    // pooling + similarity
    pool_kernel<<<dim3(128, 2), 256>>>(b2, Ncnt);
    sim_kernel<<<1, 256>>>(out, osz);
}

// round 16
// speedup vs baseline: 1.0976x; 1.0976x over previous
#include <cuda_runtime.h>
#include <math.h>
#include <stdint.h>

#define NN    10000
#define EEMAX 320000
#define ETOTM (EEMAX + NN)

// ---------------- scratch: double-buffered per branch ----------------
__device__ __align__(16) float g_h1[2 * NN * 384];
__device__ __align__(16) float g_s1[2 * NN * 3];
__device__ __align__(16) float g_d1[2 * NN * 3];
__device__ __align__(16) float g_rden1[2 * NN * 3];
__device__ __align__(16) float g_agg1[2 * NN * 384];
__device__ __align__(16) float g_h2[2 * NN * 128];
__device__ __align__(16) float g_s2[2 * NN];
__device__ __align__(16) float g_d2[2 * NN];
__device__ __align__(16) float g_exp1[2 * 3 * ETOTM];
__device__ __align__(16) float g_exp2[2 * ETOTM];
__device__ __align__(16) float g_agg2[2 * NN * 128];
__device__ __align__(16) float g_pool[2 * 256];
// fused attention weight vectors (fp32-exact alpha path)
__device__ __align__(16) float g_ws1[256 * 3];
__device__ __align__(16) float g_wd1[256 * 3];
__device__ __align__(16) float g_ws2[384];
__device__ __align__(16) float g_wd2[384];
// CSR per branch
__device__ int g_deg[2 * NN];
__device__ int g_off[2 * (NN + 1)];
__device__ int g_fill[2 * NN];
__device__ int g_esrc[2 * ETOTM];

// ---------------- tf32 helpers ----------------
__device__ __forceinline__ float to_tf32(float x)
{
    uint32_t u;
    asm("cvt.rna.tf32.f32 %0, %1;" : "=r"(u) : "f"(x));
    return __uint_as_float(u);
}

__device__ __forceinline__ void mma_tf32(float d[4],
    uint32_t a0, uint32_t a1, uint32_t a2, uint32_t a3, uint32_t b0, uint32_t b1)
{
    asm volatile(
        "mma.sync.aligned.m16n8k8.row.col.f32.tf32.tf32.f32 "
        "{%0,%1,%2,%3}, {%4,%5,%6,%7}, {%8,%9}, {%0,%1,%2,%3};"
        : "+f"(d[0]), "+f"(d[1]), "+f"(d[2]), "+f"(d[3])
        : "r"(a0), "r"(a1), "r"(a2), "r"(a3), "r"(b0), "r"(b1));
}

// ---------------- prep: fused attention weight vectors ----------------
// block 0: ws1/wd1[k][h] = sum_c W1[k, h*128+c] * a{s,d}1[h][c]   (768 threads)
// block 1: ws2/wd2[k]    = sum_c W2[k, c] * a{s,d}2[c]            (384 threads)
__global__ void prep_att(const float* __restrict__ W1,
                         const float* __restrict__ as1, const float* __restrict__ ad1,
                         const float* __restrict__ W2,
                         const float* __restrict__ as2, const float* __restrict__ ad2)
{
    int t = threadIdx.x;
    if (blockIdx.x == 0) {
        if (t >= 768) return;
        int k = t / 3, h = t - k * 3;
        const float* wr = W1 + (size_t)k * 384 + h * 128;
        const float* sa = as1 + h * 128;
        const float* da = ad1 + h * 128;
        float s = 0.f, d = 0.f;
        #pragma unroll 8
        for (int c = 0; c < 128; c++) { float w = wr[c]; s += w * sa[c]; d += w * da[c]; }
        g_ws1[k * 3 + h] = s;
        g_wd1[k * 3 + h] = d;
    } else {
        if (t >= 384) return;
        const float* wr = W2 + (size_t)t * 128;
        float s = 0.f, d = 0.f;
        #pragma unroll 8
        for (int c = 0; c < 128; c++) { float w = wr[c]; s += w * as2[c]; d += w * ad2[c]; }
        g_ws2[t] = s;
        g_wd2[t] = d;
    }
}

// ---------------- CSR build ----------------
__global__ void init_deg(int Ncnt)
{
    int i = blockIdx.x * blockDim.x + threadIdx.x;
    if (i < 2 * Ncnt) g_deg[i] = 0;
}

__global__ void csr_count(const int* __restrict__ ei1, const int* __restrict__ ei2,
                          int E, int Ncnt)
{
    int t = blockIdx.x * blockDim.x + threadIdx.x;
    int Etot = E + Ncnt;
    if (t >= 2 * Etot) return;
    int b = (t >= Etot) ? 1 : 0;
    int e = t - b * Etot;
    const int* ei = b ? ei2 : ei1;
    int dst = (e < E) ? ei[E + e] : (e - E);
    dst = min(max(dst, 0), Ncnt - 1);
    atomicAdd(&g_deg[b * NN + dst], 1);
}

__global__ void csr_scan(int Ncnt, int Etot)
{
    __shared__ int part[1024];
    int b = blockIdx.x;
    int* deg = g_deg + b * NN;
    int* off = g_off + b * (NN + 1);
    int* fil = g_fill + b * NN;
    int t = threadIdx.x;
    int chunk = (Ncnt + 1023) / 1024;
    int s0 = t * chunk;
    int s1 = min(s0 + chunk, Ncnt);
    int s = 0;
    for (int i = s0; i < s1; i++) s += deg[i];
    part[t] = s;
    __syncthreads();
    for (int o = 1; o < 1024; o <<= 1) {
        int v = (t >= o) ? part[t - o] : 0;
        __syncthreads();
        part[t] += v;
        __syncthreads();
    }
    int run = part[t] - s;
    for (int i = s0; i < s1; i++) {
        off[i] = run;
        fil[i] = run;
        run += deg[i];
    }
    if (t == 0) off[Ncnt] = Etot;
}

__global__ void csr_scatter(const int* __restrict__ ei1, const int* __restrict__ ei2,
                            int E, int Ncnt)
{
    int t = blockIdx.x * blockDim.x + threadIdx.x;
    int Etot = E + Ncnt;
    if (t >= 2 * Etot) return;
    int b = (t >= Etot) ? 1 : 0;
    int e = t - b * Etot;
    const int* ei = b ? ei2 : ei1;
    int src, dst;
    if (e < E) { src = ei[e]; dst = ei[E + e]; }
    else       { src = e - E; dst = src; }
    src = min(max(src, 0), Ncnt - 1);
    dst = min(max(dst, 0), Ncnt - 1);
    int pos = atomicAdd(&g_fill[b * NN + dst], 1);
    g_esrc[b * ETOTM + pos] = src;
}

// ---------------- tf32 GEMM1: h1[b][M,384] = x_b @ W1 ----------------
// 128x128 tile, BK=16, 8 warps (2x4), 4x4 m16n8k8 tiles per warp.
__global__ __launch_bounds__(256) void gemm_l1_tf32(const float* __restrict__ A1,
                                                    const float* __restrict__ A2,
                                                    const float* __restrict__ B, int M)
{
    const int N = 384, K = 256;
    __shared__ float As[16][136];   // [k][m], tf32 values
    __shared__ float Bs[16][136];   // [k][n], tf32 values
    const int tid = threadIdx.x;
    const int lane = tid & 31, warp = tid >> 5;
    const int gid = lane >> 2, tig = lane & 3;
    const int warp_m = warp >> 2, warp_n = warp & 3;   // 2 x 4
    const int row0 = blockIdx.y * 128, col0 = blockIdx.x * 128;
    const float* A = blockIdx.z ? A2 : A1;
    float* H = g_h1 + (size_t)blockIdx.z * NN * 384;

    const int ar = tid >> 1, ac = (tid & 1) * 8;
    const int br = tid >> 4, bc = (tid & 15) * 8;
    const int arow = row0 + ar;

    float acc[4][4][4];
    #pragma unroll
    for (int i = 0; i < 4; i++)
        #pragma unroll
        for (int j = 0; j < 4; j++)
            #pragma unroll
            for (int r = 0; r < 4; r++) acc[i][j][r] = 0.f;

    for (int k0 = 0; k0 < K; k0 += 16) {
        {
            float4 a0 = make_float4(0.f, 0.f, 0.f, 0.f), a1v = a0;
            if (arow < M) {
                a0  = *(const float4*)(A + (size_t)arow * K + k0 + ac);
                a1v = *(const float4*)(A + (size_t)arow * K + k0 + ac + 4);
            }
            As[ac + 0][ar] = to_tf32(a0.x);  As[ac + 1][ar] = to_tf32(a0.y);
            As[ac + 2][ar] = to_tf32(a0.z);  As[ac + 3][ar] = to_tf32(a0.w);
            As[ac + 4][ar] = to_tf32(a1v.x); As[ac + 5][ar] = to_tf32(a1v.y);
            As[ac + 6][ar] = to_tf32(a1v.z); As[ac + 7][ar] = to_tf32(a1v.w);

            float4 b0 = *(const float4*)(B + (size_t)(k0 + br) * N + col0 + bc);
            float4 b1v = *(const float4*)(B + (size_t)(k0 + br) * N + col0 + bc + 4);
            Bs[br][bc + 0] = to_tf32(b0.x);  Bs[br][bc + 1] = to_tf32(b0.y);
            Bs[br][bc + 2] = to_tf32(b0.z);  Bs[br][bc + 3] = to_tf32(b0.w);
            Bs[br][bc + 4] = to_tf32(b1v.x); Bs[br][bc + 5] = to_tf32(b1v.y);
            Bs[br][bc + 6] = to_tf32(b1v.z); Bs[br][bc + 7] = to_tf32(b1v.w);
        }
        __syncthreads();

        #pragma unroll
        for (int k8 = 0; k8 < 16; k8 += 8) {
            uint32_t afr[4][4];
            #pragma unroll
            for (int tm = 0; tm < 4; tm++) {
                int m0 = warp_m * 64 + tm * 16;
                afr[tm][0] = __float_as_uint(As[k8 + tig][m0 + gid]);
                afr[tm][1] = __float_as_uint(As[k8 + tig][m0 + gid + 8]);
                afr[tm][2] = __float_as_uint(As[k8 + tig + 4][m0 + gid]);
                afr[tm][3] = __float_as_uint(As[k8 + tig + 4][m0 + gid + 8]);
            }
            uint32_t bfr[4][2];
            #pragma unroll
            for (int tn = 0; tn < 4; tn++) {
                int n0 = warp_n * 32 + tn * 8;
                bfr[tn][0] = __float_as_uint(Bs[k8 + tig][n0 + gid]);
                bfr[tn][1] = __float_as_uint(Bs[k8 + tig + 4][n0 + gid]);
            }
            #pragma unroll
            for (int tm = 0; tm < 4; tm++)
                #pragma unroll
                for (int tn = 0; tn < 4; tn++)
                    mma_tf32(acc[tm][tn], afr[tm][0], afr[tm][1], afr[tm][2], afr[tm][3],
                             bfr[tn][0], bfr[tn][1]);
        }
        __syncthreads();
    }

    #pragma unroll
    for (int tm = 0; tm < 4; tm++) {
        int r0 = row0 + warp_m * 64 + tm * 16 + gid;
        int r1 = r0 + 8;
        #pragma unroll
        for (int tn = 0; tn < 4; tn++) {
            int c = col0 + warp_n * 32 + tn * 8 + tig * 2;
            if (r0 < M) *(float2*)(H + (size_t)r0 * N + c) = make_float2(acc[tm][tn][0], acc[tm][tn][1]);
            if (r1 < M) *(float2*)(H + (size_t)r1 * N + c) = make_float2(acc[tm][tn][2], acc[tm][tn][3]);
        }
    }
}

// ---------------- tf32 GEMM2: h2[b][M,128] = relu(agg1+b1) @ W2 ----------------
__global__ __launch_bounds__(256) void gemm_l2_tf32(const float* __restrict__ B,
                                                    const float* __restrict__ abias, int M)
{
    const int N = 128, K = 384;
    __shared__ float As[16][136];
    __shared__ float Bs[16][136];
    const int tid = threadIdx.x;
    const int lane = tid & 31, warp = tid >> 5;
    const int gid = lane >> 2, tig = lane & 3;
    const int warp_m = warp >> 2, warp_n = warp & 3;
    const int row0 = blockIdx.y * 128;
    const float* AG = g_agg1 + (size_t)blockIdx.z * NN * 384;
    float* H = g_h2 + (size_t)blockIdx.z * NN * 128;

    const int ar = tid >> 1, ac = (tid & 1) * 8;
    const int br = tid >> 4, bc = (tid & 15) * 8;
    const int arow = row0 + ar;

    float acc[4][4][4];
    #pragma unroll
    for (int i = 0; i < 4; i++)
        #pragma unroll
        for (int j = 0; j < 4; j++)
            #pragma unroll
            for (int r = 0; r < 4; r++) acc[i][j][r] = 0.f;

    for (int k0 = 0; k0 < K; k0 += 16) {
        {
            float4 a0 = make_float4(0.f, 0.f, 0.f, 0.f), a1v = a0;
            if (arow < M) {
                a0  = *(const float4*)(AG + (size_t)arow * K + k0 + ac);
                a1v = *(const float4*)(AG + (size_t)arow * K + k0 + ac + 4);
                a0.x = fmaxf(a0.x + abias[k0 + ac + 0], 0.f);
                a0.y = fmaxf(a0.y + abias[k0 + ac + 1], 0.f);
                a0.z = fmaxf(a0.z + abias[k0 + ac + 2], 0.f);
                a0.w = fmaxf(a0.w + abias[k0 + ac + 3], 0.f);
                a1v.x = fmaxf(a1v.x + abias[k0 + ac + 4], 0.f);
                a1v.y = fmaxf(a1v.y + abias[k0 + ac + 5], 0.f);
                a1v.z = fmaxf(a1v.z + abias[k0 + ac + 6], 0.f);
                a1v.w = fmaxf(a1v.w + abias[k0 + ac + 7], 0.f);
            }
            As[ac + 0][ar] = to_tf32(a0.x);  As[ac + 1][ar] = to_tf32(a0.y);
            As[ac + 2][ar] = to_tf32(a0.z);  As[ac + 3][ar] = to_tf32(a0.w);
            As[ac + 4][ar] = to_tf32(a1v.x); As[ac + 5][ar] = to_tf32(a1v.y);
            As[ac + 6][ar] = to_tf32(a1v.z); As[ac + 7][ar] = to_tf32(a1v.w);

            float4 b0 = *(const float4*)(B + (size_t)(k0 + br) * N + bc);
            float4 b1v = *(const float4*)(B + (size_t)(k0 + br) * N + bc + 4);
            Bs[br][bc + 0] = to_tf32(b0.x);  Bs[br][bc + 1] = to_tf32(b0.y);
            Bs[br][bc + 2] = to_tf32(b0.z);  Bs[br][bc + 3] = to_tf32(b0.w);
            Bs[br][bc + 4] = to_tf32(b1v.x); Bs[br][bc + 5] = to_tf32(b1v.y);
            Bs[br][bc + 6] = to_tf32(b1v.z); Bs[br][bc + 7] = to_tf32(b1v.w);
        }
        __syncthreads();

        #pragma unroll
        for (int k8 = 0; k8 < 16; k8 += 8) {
            uint32_t afr[4][4];
            #pragma unroll
            for (int tm = 0; tm < 4; tm++) {
                int m0 = warp_m * 64 + tm * 16;
                afr[tm][0] = __float_as_uint(As[k8 + tig][m0 + gid]);
                afr[tm][1] = __float_as_uint(As[k8 + tig][m0 + gid + 8]);
                afr[tm][2] = __float_as_uint(As[k8 + tig + 4][m0 + gid]);
                afr[tm][3] = __float_as_uint(As[k8 + tig + 4][m0 + gid + 8]);
            }
            uint32_t bfr[4][2];
            #pragma unroll
            for (int tn = 0; tn < 4; tn++) {
                int n0 = warp_n * 32 + tn * 8;
                bfr[tn][0] = __float_as_uint(Bs[k8 + tig][n0 + gid]);
                bfr[tn][1] = __float_as_uint(Bs[k8 + tig + 4][n0 + gid]);
            }
            #pragma unroll
            for (int tm = 0; tm < 4; tm++)
                #pragma unroll
                for (int tn = 0; tn < 4; tn++)
                    mma_tf32(acc[tm][tn], afr[tm][0], afr[tm][1], afr[tm][2], afr[tm][3],
                             bfr[tn][0], bfr[tn][1]);
        }
        __syncthreads();
    }

    #pragma unroll
    for (int tm = 0; tm < 4; tm++) {
        int r0 = row0 + warp_m * 64 + tm * 16 + gid;
        int r1 = r0 + 8;
        #pragma unroll
        for (int tn = 0; tn < 4; tn++) {
            int c = warp_n * 32 + tn * 8 + tig * 2;
            if (r0 < M) *(float2*)(H + (size_t)r0 * N + c) = make_float2(acc[tm][tn][0], acc[tm][tn][1]);
            if (r1 < M) *(float2*)(H + (size_t)r1 * N + c) = make_float2(acc[tm][tn][2], acc[tm][tn][3]);
        }
    }
}

// ---------------- s1/d1 = x @ ws1/wd1 (fp32-exact alpha path) ----------------
__global__ void sd1_x(const float* __restrict__ x1, const float* __restrict__ x2, int n)
{
    int w = (blockIdx.x * blockDim.x + threadIdx.x) >> 5;
    int lane = threadIdx.x & 31;
    if (w >= 2 * n) return;
    int b = w / n;
    int node = w - b * n;
    const float* xp = (b ? x2 : x1) + (size_t)node * 256;

    float s0 = 0.f, s1v = 0.f, s2v = 0.f, d0 = 0.f, d1v = 0.f, d2v = 0.f;
    #pragma unroll
    for (int i = 0; i < 8; i++) {
        int k = lane + i * 32;
        float xv = xp[k];
        s0  += xv * g_ws1[k * 3 + 0];
        s1v += xv * g_ws1[k * 3 + 1];
        s2v += xv * g_ws1[k * 3 + 2];
        d0  += xv * g_wd1[k * 3 + 0];
        d1v += xv * g_wd1[k * 3 + 1];
        d2v += xv * g_wd1[k * 3 + 2];
    }
    #pragma unroll
    for (int o = 16; o; o >>= 1) {
        s0  += __shfl_xor_sync(0xffffffffu, s0, o);
        s1v += __shfl_xor_sync(0xffffffffu, s1v, o);
        s2v += __shfl_xor_sync(0xffffffffu, s2v, o);
        d0  += __shfl_xor_sync(0xffffffffu, d0, o);
        d1v += __shfl_xor_sync(0xffffffffu, d1v, o);
        d2v += __shfl_xor_sync(0xffffffffu, d2v, o);
    }
    if (lane == 0) {
        int base = b * NN * 3 + node * 3;
        g_s1[base + 0] = s0;  g_s1[base + 1] = s1v; g_s1[base + 2] = s2v;
        g_d1[base + 0] = d0;  g_d1[base + 1] = d1v; g_d1[base + 2] = d2v;
    }
}

// ---------------- s2/d2 = relu(agg1+b1) @ ws2/wd2 ----------------
__global__ void sd2_ag(const float* __restrict__ abias, int n)
{
    int w = (blockIdx.x * blockDim.x + threadIdx.x) >> 5;
    int lane = threadIdx.x & 31;
    if (w >= 2 * n) return;
    int b = w / n;
    int node = w - b * n;
    const float* ap = g_agg1 + ((size_t)b * NN + node) * 384;

    float s = 0.f, d = 0.f;
    #pragma unroll
    for (int i = 0; i < 12; i++) {
        int k = lane + i * 32;
        float v = fmaxf(ap[k] + abias[k], 0.f);
        s += v * g_ws2[k];
        d += v * g_wd2[k];
    }
    #pragma unroll
    for (int o = 16; o; o >>= 1) {
        s += __shfl_xor_sync(0xffffffffu, s, o);
        d += __shfl_xor_sync(0xffffffffu, d, o);
    }
    if (lane == 0) { g_s2[b * NN + node] = s; g_d2[b * NN + node] = d; }
}

// ---------------- layer-1 softmax + aggregation ----------------
__global__ __launch_bounds__(256) void agg_l1_csr(int E, int Ncnt)
{
    int b = blockIdx.y;
    int dst = (blockIdx.x * blockDim.x + threadIdx.x) >> 5;
    int lane = threadIdx.x & 31;
    if (dst >= Ncnt) return;
    const int* off  = g_off + b * (NN + 1);
    const int* srcv = g_esrc + b * ETOTM;
    const float* s1 = g_s1 + b * NN * 3;
    float* e0p = g_exp1 + (size_t)(b * 3 + 0) * ETOTM;
    float* e1p = g_exp1 + (size_t)(b * 3 + 1) * ETOTM;
    float* e2p = g_exp1 + (size_t)(b * 3 + 2) * ETOTM;

    int beg = off[dst], end = off[dst + 1];
    float dv0 = g_d1[b * NN * 3 + dst * 3 + 0];
    float dv1 = g_d1[b * NN * 3 + dst * 3 + 1];
    float dv2 = g_d1[b * NN * 3 + dst * 3 + 2];

    float den0 = 0.f, den1 = 0.f, den2 = 0.f;
    for (int i = beg + lane; i < end; i += 32) {
        int src = srcv[i];
        float e0 = s1[src * 3 + 0] + dv0;
        float e1 = s1[src * 3 + 1] + dv1;
        float e2 = s1[src * 3 + 2] + dv2;
        e0 = e0 > 0.f ? e0 : 0.2f * e0;
        e1 = e1 > 0.f ? e1 : 0.2f * e1;
        e2 = e2 > 0.f ? e2 : 0.2f * e2;
        float x0 = expf(e0), x1 = expf(e1), x2 = expf(e2);
        e0p[i] = x0; e1p[i] = x1; e2p[i] = x2;
        den0 += x0; den1 += x1; den2 += x2;
    }
    #pragma unroll
    for (int o = 16; o; o >>= 1) {
        den0 += __shfl_xor_sync(0xffffffffu, den0, o);
        den1 += __shfl_xor_sync(0xffffffffu, den1, o);
        den2 += __shfl_xor_sync(0xffffffffu, den2, o);
    }
    float r0 = 1.f / den0, r1 = 1.f / den1, r2 = 1.f / den2;
    if (lane == 0) {
        g_rden1[b * NN * 3 + dst * 3 + 0] = r0;
        g_rden1[b * NN * 3 + dst * 3 + 1] = r1;
        g_rden1[b * NN * 3 + dst * 3 + 2] = r2;
    }
    __syncwarp();

    float acc[12];
    #pragma unroll
    for (int k = 0; k < 12; k++) acc[k] = 0.f;
    const float4* h1b = (const float4*)(g_h1 + (size_t)b * NN * 384);

    #pragma unroll 2
    for (int i = beg; i < end; i++) {
        float a0 = e0p[i] * r0, a1 = e1p[i] * r1, a2 = e2p[i] * r2;
        int src = srcv[i];
        const float4* hs = h1b + (size_t)src * 96;
        float4 v0 = hs[lane];
        float4 v1 = hs[32 + lane];
        float4 v2 = hs[64 + lane];
        acc[0] += v0.x * a0; acc[1]  += v0.y * a0; acc[2]  += v0.z * a0; acc[3]  += v0.w * a0;
        acc[4] += v1.x * a1; acc[5]  += v1.y * a1; acc[6]  += v1.z * a1; acc[7]  += v1.w * a1;
        acc[8] += v2.x * a2; acc[9]  += v2.y * a2; acc[10] += v2.z * a2; acc[11] += v2.w * a2;
    }

    float4* og = (float4*)(g_agg1 + ((size_t)b * NN + dst) * 384);
    og[lane]      = make_float4(acc[0], acc[1], acc[2], acc[3]);
    og[32 + lane] = make_float4(acc[4], acc[5], acc[6], acc[7]);
    og[64 + lane] = make_float4(acc[8], acc[9], acc[10], acc[11]);
}

// ---------------- alpha output: edge-parallel, original order ----------------
__global__ void alpha_l1(const int* __restrict__ ei1, const int* __restrict__ ei2,
                         int E, int Ncnt, float* __restrict__ out, long long out_size)
{
    int t = blockIdx.x * blockDim.x + threadIdx.x;
    int Etot = E + Ncnt;
    if (t >= 2 * Etot) return;
    int b = (t >= Etot) ? 1 : 0;
    int e = t - b * Etot;
    const int* ei = b ? ei2 : ei1;
    int src, dst;
    if (e < E) { src = ei[e]; dst = ei[E + e]; }
    else       { src = e - E; dst = src; }
    src = min(max(src, 0), Ncnt - 1);
    dst = min(max(dst, 0), Ncnt - 1);

    const float* s1 = g_s1 + b * NN * 3;
    const float* d1 = g_d1 + b * NN * 3;
    const float* rd = g_rden1 + b * NN * 3;
    long long ob = 1 + (long long)b * Etot * 3 + 3LL * e;
    if (ob + 2 >= out_size) return;

    #pragma unroll
    for (int h = 0; h < 3; h++) {
        float v = s1[src * 3 + h] + d1[dst * 3 + h];
        v = v > 0.f ? v : 0.2f * v;
        out[ob + h] = expf(v) * rd[dst * 3 + h];
    }
}

// ---------------- layer-2 softmax + aggregation ----------------
__global__ __launch_bounds__(256) void agg_l2_csr(int E, int Ncnt)
{
    int b = blockIdx.y;
    int dst = (blockIdx.x * blockDim.x + threadIdx.x) >> 5;
    int lane = threadIdx.x & 31;
    if (dst >= Ncnt) return;
    const int* off  = g_off + b * (NN + 1);
    const int* srcv = g_esrc + b * ETOTM;
    const float* s2 = g_s2 + b * NN;
    float* xp = g_exp2 + (size_t)b * ETOTM;

    int beg = off[dst], end = off[dst + 1];
    float dv = g_d2[b * NN + dst];
    float den = 0.f;
    for (int i = beg + lane; i < end; i += 32) {
        int src = srcv[i];
        float e = s2[src] + dv;
        e = e > 0.f ? e : 0.2f * e;
        float x = expf(e);
        xp[i] = x;
        den += x;
    }
    #pragma unroll
    for (int o = 16; o; o >>= 1) den += __shfl_xor_sync(0xffffffffu, den, o);
    float r = 1.f / den;
    __syncwarp();

    float4 acc = make_float4(0.f, 0.f, 0.f, 0.f);
    const float4* h2b = (const float4*)(g_h2 + (size_t)b * NN * 128);
    #pragma unroll 2
    for (int i = beg; i < end; i++) {
        float a = xp[i] * r;
        int src = srcv[i];
        float4 v = h2b[(size_t)src * 32 + lane];
        acc.x += v.x * a; acc.y += v.y * a; acc.z += v.z * a; acc.w += v.w * a;
    }
    ((float4*)(g_agg2 + ((size_t)b * NN + dst) * 128))[lane] = acc;
}

// ---------------- pooling (node_attn == 1 identically) ----------------
__global__ void pool_kernel(const float* __restrict__ b2, int Ncnt)
{
    int c = blockIdx.x;
    int b = blockIdx.y;
    const float* ag = g_agg2 + (size_t)b * NN * 128;
    float bias = b2[c];
    float se = 0.f;
    for (int n = threadIdx.x; n < Ncnt; n += blockDim.x)
        se += ag[(size_t)n * 128 + c] + bias;
    __shared__ float r1[256];
    r1[threadIdx.x] = se;
    __syncthreads();
    for (int o = 128; o; o >>= 1) {
        if (threadIdx.x < o) r1[threadIdx.x] += r1[threadIdx.x + o];
        __syncthreads();
    }
    if (threadIdx.x == 0) {
        float m = r1[0] / (float)Ncnt;
        g_pool[b * 256 + c]       = m;
        g_pool[b * 256 + 128 + c] = m;
    }
}

// ---------------- cosine similarity ----------------
__global__ void sim_kernel(float* __restrict__ out, long long out_size)
{
    int t = threadIdx.x;
    float a = g_pool[t], b = g_pool[256 + t];
    __shared__ float sd_[256], sa[256], sb[256];
    sd_[t] = a * b; sa[t] = a * a; sb[t] = b * b;
    __syncthreads();
    for (int o = 128; o; o >>= 1) {
        if (t < o) { sd_[t] += sd_[t + o]; sa[t] += sa[t + o]; sb[t] += sb[t + o]; }
        __syncthreads();
    }
    if (t == 0 && out_size >= 1) {
        float n1 = fmaxf(sqrtf(sa[0]), 1e-8f);
        float n2 = fmaxf(sqrtf(sb[0]), 1e-8f);
        out[0] = sd_[0] / (n1 * n2);
    }
}

// ---------------- host launcher ----------------
extern "C" void kernel_launch(void* const* d_in, const int* in_sizes, int n_in,
                              void* d_out, int out_size)
{
    const float* x1  = (const float*)d_in[0];
    const int*   ei1 = (const int*)d_in[1];     // int32
    const float* x2  = (const float*)d_in[2];
    const int*   ei2 = (const int*)d_in[3];
    const float* W1  = (const float*)d_in[4];
    const float* as1 = (const float*)d_in[5];
    const float* ad1 = (const float*)d_in[6];
    const float* b1  = (const float*)d_in[7];
    const float* W2  = (const float*)d_in[8];
    const float* as2 = (const float*)d_in[9];
    const float* ad2 = (const float*)d_in[10];
    const float* b2  = (const float*)d_in[11];
    float* out = (float*)d_out;
    const long long osz = (long long)out_size;

    const int Ncnt = in_sizes[0] / 256;
    const int E    = in_sizes[1] / 2;
    const int Etot = E + Ncnt;

    const int e2blocks = (2 * Etot + 255) / 256;
    const int nwb = (Ncnt * 32 + 255) / 256;
    const int sdb = (2 * Ncnt * 32 + 255) / 256;

    // fused attention weight vectors + CSR build
    prep_att<<<2, 768>>>(W1, as1, ad1, W2, as2, ad2);
    init_deg<<<(2 * Ncnt + 255) / 256, 256>>>(Ncnt);
    csr_count<<<e2blocks, 256>>>(ei1, ei2, E, Ncnt);
    csr_scan<<<2, 1024>>>(Ncnt, Etot);
    csr_scatter<<<e2blocks, 256>>>(ei1, ei2, E, Ncnt);

    // layer 1
    gemm_l1_tf32<<<dim3(3, (Ncnt + 127) / 128, 2), 256>>>(x1, x2, W1, Ncnt);
    sd1_x<<<sdb, 256>>>(x1, x2, Ncnt);
    agg_l1_csr<<<dim3(nwb, 2), 256>>>(E, Ncnt);
    alpha_l1<<<e2blocks, 256>>>(ei1, ei2, E, Ncnt, out, osz);

    // layer 2
    gemm_l2_tf32<<<dim3(1, (Ncnt + 127) / 128, 2), 256>>>(W2, b1, Ncnt);
    sd2_ag<<<sdb, 256>>>(b1, Ncnt);
    agg_l2_csr<<<dim3(nwb, 2), 256>>>(E, Ncnt);

    // pooling + similarity
    pool_kernel<<<dim3(128, 2), 256>>>(b2, Ncnt);
    sim_kernel<<<1, 256>>>(out, osz);
}

// round 17
// speedup vs baseline: 1.1919x; 1.0859x over previous
#include <cuda_runtime.h>
#include <math.h>
#include <stdint.h>

#define NN    10000
#define EEMAX 320000
#define ETOTM (EEMAX + NN)

// ---------------- scratch: double-buffered per branch ----------------
__device__ __align__(16) float g_h1[2 * NN * 384];
__device__ __align__(16) float g_s1[2 * NN * 3];
__device__ __align__(16) float g_d1[2 * NN * 3];
__device__ __align__(16) float g_rden1[2 * NN * 3];
__device__ __align__(16) float g_agg1[2 * NN * 384];
__device__ __align__(16) float g_h2[2 * NN * 128];
__device__ __align__(16) float g_s2[2 * NN];
__device__ __align__(16) float g_d2[2 * NN];
__device__ __align__(16) float g_exp1[2 * 3 * ETOTM];
__device__ __align__(16) float g_exp2[2 * ETOTM];
__device__ __align__(16) float g_agg2[2 * NN * 128];
__device__ __align__(16) float g_pool[2 * 256];
// fused attention weight vectors (fp32-exact alpha path)
__device__ __align__(16) float g_ws1[256 * 3];
__device__ __align__(16) float g_wd1[256 * 3];
__device__ __align__(16) float g_ws2[384];
__device__ __align__(16) float g_wd2[384];
// CSR per branch
__device__ int g_deg[2 * NN];
__device__ int g_off[2 * (NN + 1)];
__device__ int g_fill[2 * NN];
__device__ int g_esrc[2 * ETOTM];

// ---------------- tf32 helpers ----------------
__device__ __forceinline__ float to_tf32(float x)
{
    uint32_t u;
    asm("cvt.rna.tf32.f32 %0, %1;" : "=r"(u) : "f"(x));
    return __uint_as_float(u);
}

__device__ __forceinline__ void mma_tf32(float d[4],
    uint32_t a0, uint32_t a1, uint32_t a2, uint32_t a3, uint32_t b0, uint32_t b1)
{
    asm volatile(
        "mma.sync.aligned.m16n8k8.row.col.f32.tf32.tf32.f32 "
        "{%0,%1,%2,%3}, {%4,%5,%6,%7}, {%8,%9}, {%0,%1,%2,%3};"
        : "+f"(d[0]), "+f"(d[1]), "+f"(d[2]), "+f"(d[3])
        : "r"(a0), "r"(a1), "r"(a2), "r"(a3), "r"(b0), "r"(b1));
}

// ---------------- prep: fused attention weight vectors ----------------
__global__ void prep_att(const float* __restrict__ W1,
                         const float* __restrict__ as1, const float* __restrict__ ad1,
                         const float* __restrict__ W2,
                         const float* __restrict__ as2, const float* __restrict__ ad2)
{
    int t = threadIdx.x;
    if (blockIdx.x == 0) {
        if (t >= 768) return;
        int k = t / 3, h = t - k * 3;
        const float* wr = W1 + (size_t)k * 384 + h * 128;
        const float* sa = as1 + h * 128;
        const float* da = ad1 + h * 128;
        float s = 0.f, d = 0.f;
        #pragma unroll 8
        for (int c = 0; c < 128; c++) { float w = wr[c]; s += w * sa[c]; d += w * da[c]; }
        g_ws1[k * 3 + h] = s;
        g_wd1[k * 3 + h] = d;
    } else {
        if (t >= 384) return;
        const float* wr = W2 + (size_t)t * 128;
        float s = 0.f, d = 0.f;
        #pragma unroll 8
        for (int c = 0; c < 128; c++) { float w = wr[c]; s += w * as2[c]; d += w * ad2[c]; }
        g_ws2[t] = s;
        g_wd2[t] = d;
    }
}

// ---------------- CSR build ----------------
__global__ void init_deg(int Ncnt)
{
    int i = blockIdx.x * blockDim.x + threadIdx.x;
    if (i < 2 * Ncnt) g_deg[i] = 0;
}

__global__ void csr_count(const int* __restrict__ ei1, const int* __restrict__ ei2,
                          int E, int Ncnt)
{
    int t = blockIdx.x * blockDim.x + threadIdx.x;
    int Etot = E + Ncnt;
    if (t >= 2 * Etot) return;
    int b = (t >= Etot) ? 1 : 0;
    int e = t - b * Etot;
    const int* ei = b ? ei2 : ei1;
    int dst = (e < E) ? ei[E + e] : (e - E);
    dst = min(max(dst, 0), Ncnt - 1);
    atomicAdd(&g_deg[b * NN + dst], 1);
}

// shared-staged scan: coalesced global access, per-chunk serial work in SMEM
__global__ void csr_scan(int Ncnt, int Etot)
{
    __shared__ int sdeg[NN];
    __shared__ int part[1024];
    int b = blockIdx.x;
    const int* deg = g_deg + b * NN;
    int* off = g_off + b * (NN + 1);
    int* fil = g_fill + b * NN;
    int t = threadIdx.x;

    for (int i = t; i < Ncnt; i += 1024) sdeg[i] = deg[i];
    __syncthreads();

    int chunk = (Ncnt + 1023) / 1024;
    int s0 = t * chunk, s1 = min(s0 + chunk, Ncnt);
    int s = 0;
    for (int i = s0; i < s1; i++) s += sdeg[i];
    part[t] = s;
    __syncthreads();
    for (int o = 1; o < 1024; o <<= 1) {
        int v = (t >= o) ? part[t - o] : 0;
        __syncthreads();
        part[t] += v;
        __syncthreads();
    }
    int run = part[t] - s;   // exclusive prefix of this chunk
    for (int i = s0; i < s1; i++) { int d = sdeg[i]; sdeg[i] = run; run += d; }
    __syncthreads();

    for (int i = t; i < Ncnt; i += 1024) { int v = sdeg[i]; off[i] = v; fil[i] = v; }
    if (t == 0) off[Ncnt] = Etot;
}

__global__ void csr_scatter(const int* __restrict__ ei1, const int* __restrict__ ei2,
                            int E, int Ncnt)
{
    int t = blockIdx.x * blockDim.x + threadIdx.x;
    int Etot = E + Ncnt;
    if (t >= 2 * Etot) return;
    int b = (t >= Etot) ? 1 : 0;
    int e = t - b * Etot;
    const int* ei = b ? ei2 : ei1;
    int src, dst;
    if (e < E) { src = ei[e]; dst = ei[E + e]; }
    else       { src = e - E; dst = src; }
    src = min(max(src, 0), Ncnt - 1);
    dst = min(max(dst, 0), Ncnt - 1);
    int pos = atomicAdd(&g_fill[b * NN + dst], 1);
    g_esrc[b * ETOTM + pos] = src;
}

// ---------------- tf32 GEMM1: h1[b][M,384] = x_b @ W1 ----------------
__global__ __launch_bounds__(256) void gemm_l1_tf32(const float* __restrict__ A1,
                                                    const float* __restrict__ A2,
                                                    const float* __restrict__ B, int M)
{
    const int N = 384, K = 256;
    __shared__ float As[16][136];
    __shared__ float Bs[16][136];
    const int tid = threadIdx.x;
    const int lane = tid & 31, warp = tid >> 5;
    const int gid = lane >> 2, tig = lane & 3;
    const int warp_m = warp >> 2, warp_n = warp & 3;
    const int row0 = blockIdx.y * 128, col0 = blockIdx.x * 128;
    const float* A = blockIdx.z ? A2 : A1;
    float* H = g_h1 + (size_t)blockIdx.z * NN * 384;

    const int ar = tid >> 1, ac = (tid & 1) * 8;
    const int br = tid >> 4, bc = (tid & 15) * 8;
    const int arow = row0 + ar;

    float acc[4][4][4];
    #pragma unroll
    for (int i = 0; i < 4; i++)
        #pragma unroll
        for (int j = 0; j < 4; j++)
            #pragma unroll
            for (int r = 0; r < 4; r++) acc[i][j][r] = 0.f;

    for (int k0 = 0; k0 < K; k0 += 16) {
        {
            float4 a0 = make_float4(0.f, 0.f, 0.f, 0.f), a1v = a0;
            if (arow < M) {
                a0  = *(const float4*)(A + (size_t)arow * K + k0 + ac);
                a1v = *(const float4*)(A + (size_t)arow * K + k0 + ac + 4);
            }
            As[ac + 0][ar] = to_tf32(a0.x);  As[ac + 1][ar] = to_tf32(a0.y);
            As[ac + 2][ar] = to_tf32(a0.z);  As[ac + 3][ar] = to_tf32(a0.w);
            As[ac + 4][ar] = to_tf32(a1v.x); As[ac + 5][ar] = to_tf32(a1v.y);
            As[ac + 6][ar] = to_tf32(a1v.z); As[ac + 7][ar] = to_tf32(a1v.w);

            float4 b0 = *(const float4*)(B + (size_t)(k0 + br) * N + col0 + bc);
            float4 b1v = *(const float4*)(B + (size_t)(k0 + br) * N + col0 + bc + 4);
            Bs[br][bc + 0] = to_tf32(b0.x);  Bs[br][bc + 1] = to_tf32(b0.y);
            Bs[br][bc + 2] = to_tf32(b0.z);  Bs[br][bc + 3] = to_tf32(b0.w);
            Bs[br][bc + 4] = to_tf32(b1v.x); Bs[br][bc + 5] = to_tf32(b1v.y);
            Bs[br][bc + 6] = to_tf32(b1v.z); Bs[br][bc + 7] = to_tf32(b1v.w);
        }
        __syncthreads();

        #pragma unroll
        for (int k8 = 0; k8 < 16; k8 += 8) {
            uint32_t afr[4][4];
            #pragma unroll
            for (int tm = 0; tm < 4; tm++) {
                int m0 = warp_m * 64 + tm * 16;
                afr[tm][0] = __float_as_uint(As[k8 + tig][m0 + gid]);
                afr[tm][1] = __float_as_uint(As[k8 + tig][m0 + gid + 8]);
                afr[tm][2] = __float_as_uint(As[k8 + tig + 4][m0 + gid]);
                afr[tm][3] = __float_as_uint(As[k8 + tig + 4][m0 + gid + 8]);
            }
            uint32_t bfr[4][2];
            #pragma unroll
            for (int tn = 0; tn < 4; tn++) {
                int n0 = warp_n * 32 + tn * 8;
                bfr[tn][0] = __float_as_uint(Bs[k8 + tig][n0 + gid]);
                bfr[tn][1] = __float_as_uint(Bs[k8 + tig + 4][n0 + gid]);
            }
            #pragma unroll
            for (int tm = 0; tm < 4; tm++)
                #pragma unroll
                for (int tn = 0; tn < 4; tn++)
                    mma_tf32(acc[tm][tn], afr[tm][0], afr[tm][1], afr[tm][2], afr[tm][3],
                             bfr[tn][0], bfr[tn][1]);
        }
        __syncthreads();
    }

    #pragma unroll
    for (int tm = 0; tm < 4; tm++) {
        int r0 = row0 + warp_m * 64 + tm * 16 + gid;
        int r1 = r0 + 8;
        #pragma unroll
        for (int tn = 0; tn < 4; tn++) {
            int c = col0 + warp_n * 32 + tn * 8 + tig * 2;
            if (r0 < M) *(float2*)(H + (size_t)r0 * N + c) = make_float2(acc[tm][tn][0], acc[tm][tn][1]);
            if (r1 < M) *(float2*)(H + (size_t)r1 * N + c) = make_float2(acc[tm][tn][2], acc[tm][tn][3]);
        }
    }
}

// ---------------- tf32 GEMM2: h2[b][M,128] = relu(agg1+b1) @ W2 ----------------
__global__ __launch_bounds__(256) void gemm_l2_tf32(const float* __restrict__ B,
                                                    const float* __restrict__ abias, int M)
{
    const int N = 128, K = 384;
    __shared__ float As[16][136];
    __shared__ float Bs[16][136];
    const int tid = threadIdx.x;
    const int lane = tid & 31, warp = tid >> 5;
    const int gid = lane >> 2, tig = lane & 3;
    const int warp_m = warp >> 2, warp_n = warp & 3;
    const int row0 = blockIdx.y * 128;
    const float* AG = g_agg1 + (size_t)blockIdx.z * NN * 384;
    float* H = g_h2 + (size_t)blockIdx.z * NN * 128;

    const int ar = tid >> 1, ac = (tid & 1) * 8;
    const int br = tid >> 4, bc = (tid & 15) * 8;
    const int arow = row0 + ar;

    float acc[4][4][4];
    #pragma unroll
    for (int i = 0; i < 4; i++)
        #pragma unroll
        for (int j = 0; j < 4; j++)
            #pragma unroll
            for (int r = 0; r < 4; r++) acc[i][j][r] = 0.f;

    for (int k0 = 0; k0 < K; k0 += 16) {
        {
            float4 a0 = make_float4(0.f, 0.f, 0.f, 0.f), a1v = a0;
            if (arow < M) {
                a0  = *(const float4*)(AG + (size_t)arow * K + k0 + ac);
                a1v = *(const float4*)(AG + (size_t)arow * K + k0 + ac + 4);
                a0.x = fmaxf(a0.x + abias[k0 + ac + 0], 0.f);
                a0.y = fmaxf(a0.y + abias[k0 + ac + 1], 0.f);
                a0.z = fmaxf(a0.z + abias[k0 + ac + 2], 0.f);
                a0.w = fmaxf(a0.w + abias[k0 + ac + 3], 0.f);
                a1v.x = fmaxf(a1v.x + abias[k0 + ac + 4], 0.f);
                a1v.y = fmaxf(a1v.y + abias[k0 + ac + 5], 0.f);
                a1v.z = fmaxf(a1v.z + abias[k0 + ac + 6], 0.f);
                a1v.w = fmaxf(a1v.w + abias[k0 + ac + 7], 0.f);
            }
            As[ac + 0][ar] = to_tf32(a0.x);  As[ac + 1][ar] = to_tf32(a0.y);
            As[ac + 2][ar] = to_tf32(a0.z);  As[ac + 3][ar] = to_tf32(a0.w);
            As[ac + 4][ar] = to_tf32(a1v.x); As[ac + 5][ar] = to_tf32(a1v.y);
            As[ac + 6][ar] = to_tf32(a1v.z); As[ac + 7][ar] = to_tf32(a1v.w);

            float4 b0 = *(const float4*)(B + (size_t)(k0 + br) * N + bc);
            float4 b1v = *(const float4*)(B + (size_t)(k0 + br) * N + bc + 4);
            Bs[br][bc + 0] = to_tf32(b0.x);  Bs[br][bc + 1] = to_tf32(b0.y);
            Bs[br][bc + 2] = to_tf32(b0.z);  Bs[br][bc + 3] = to_tf32(b0.w);
            Bs[br][bc + 4] = to_tf32(b1v.x); Bs[br][bc + 5] = to_tf32(b1v.y);
            Bs[br][bc + 6] = to_tf32(b1v.z); Bs[br][bc + 7] = to_tf32(b1v.w);
        }
        __syncthreads();

        #pragma unroll
        for (int k8 = 0; k8 < 16; k8 += 8) {
            uint32_t afr[4][4];
            #pragma unroll
            for (int tm = 0; tm < 4; tm++) {
                int m0 = warp_m * 64 + tm * 16;
                afr[tm][0] = __float_as_uint(As[k8 + tig][m0 + gid]);
                afr[tm][1] = __float_as_uint(As[k8 + tig][m0 + gid + 8]);
                afr[tm][2] = __float_as_uint(As[k8 + tig + 4][m0 + gid]);
                afr[tm][3] = __float_as_uint(As[k8 + tig + 4][m0 + gid + 8]);
            }
            uint32_t bfr[4][2];
            #pragma unroll
            for (int tn = 0; tn < 4; tn++) {
                int n0 = warp_n * 32 + tn * 8;
                bfr[tn][0] = __float_as_uint(Bs[k8 + tig][n0 + gid]);
                bfr[tn][1] = __float_as_uint(Bs[k8 + tig + 4][n0 + gid]);
            }
            #pragma unroll
            for (int tm = 0; tm < 4; tm++)
                #pragma unroll
                for (int tn = 0; tn < 4; tn++)
                    mma_tf32(acc[tm][tn], afr[tm][0], afr[tm][1], afr[tm][2], afr[tm][3],
                             bfr[tn][0], bfr[tn][1]);
        }
        __syncthreads();
    }

    #pragma unroll
    for (int tm = 0; tm < 4; tm++) {
        int r0 = row0 + warp_m * 64 + tm * 16 + gid;
        int r1 = r0 + 8;
        #pragma unroll
        for (int tn = 0; tn < 4; tn++) {
            int c = warp_n * 32 + tn * 8 + tig * 2;
            if (r0 < M) *(float2*)(H + (size_t)r0 * N + c) = make_float2(acc[tm][tn][0], acc[tm][tn][1]);
            if (r1 < M) *(float2*)(H + (size_t)r1 * N + c) = make_float2(acc[tm][tn][2], acc[tm][tn][3]);
        }
    }
}

// ---------------- s1/d1 = x @ ws1/wd1 (fp32-exact alpha path) ----------------
__global__ void sd1_x(const float* __restrict__ x1, const float* __restrict__ x2, int n)
{
    int w = (blockIdx.x * blockDim.x + threadIdx.x) >> 5;
    int lane = threadIdx.x & 31;
    if (w >= 2 * n) return;
    int b = w / n;
    int node = w - b * n;
    const float* xp = (b ? x2 : x1) + (size_t)node * 256;

    float s0 = 0.f, s1v = 0.f, s2v = 0.f, d0 = 0.f, d1v = 0.f, d2v = 0.f;
    #pragma unroll
    for (int i = 0; i < 8; i++) {
        int k = lane + i * 32;
        float xv = xp[k];
        s0  += xv * g_ws1[k * 3 + 0];
        s1v += xv * g_ws1[k * 3 + 1];
        s2v += xv * g_ws1[k * 3 + 2];
        d0  += xv * g_wd1[k * 3 + 0];
        d1v += xv * g_wd1[k * 3 + 1];
        d2v += xv * g_wd1[k * 3 + 2];
    }
    #pragma unroll
    for (int o = 16; o; o >>= 1) {
        s0  += __shfl_xor_sync(0xffffffffu, s0, o);
        s1v += __shfl_xor_sync(0xffffffffu, s1v, o);
        s2v += __shfl_xor_sync(0xffffffffu, s2v, o);
        d0  += __shfl_xor_sync(0xffffffffu, d0, o);
        d1v += __shfl_xor_sync(0xffffffffu, d1v, o);
        d2v += __shfl_xor_sync(0xffffffffu, d2v, o);
    }
    if (lane == 0) {
        int base = b * NN * 3 + node * 3;
        g_s1[base + 0] = s0;  g_s1[base + 1] = s1v; g_s1[base + 2] = s2v;
        g_d1[base + 0] = d0;  g_d1[base + 1] = d1v; g_d1[base + 2] = d2v;
    }
}

// ---------------- s2/d2 = relu(agg1+b1) @ ws2/wd2 ----------------
__global__ void sd2_ag(const float* __restrict__ abias, int n)
{
    int w = (blockIdx.x * blockDim.x + threadIdx.x) >> 5;
    int lane = threadIdx.x & 31;
    if (w >= 2 * n) return;
    int b = w / n;
    int node = w - b * n;
    const float* ap = g_agg1 + ((size_t)b * NN + node) * 384;

    float s = 0.f, d = 0.f;
    #pragma unroll
    for (int i = 0; i < 12; i++) {
        int k = lane + i * 32;
        float v = fmaxf(ap[k] + abias[k], 0.f);
        s += v * g_ws2[k];
        d += v * g_wd2[k];
    }
    #pragma unroll
    for (int o = 16; o; o >>= 1) {
        s += __shfl_xor_sync(0xffffffffu, s, o);
        d += __shfl_xor_sync(0xffffffffu, d, o);
    }
    if (lane == 0) { g_s2[b * NN + node] = s; g_d2[b * NN + node] = d; }
}

// ---------------- layer-1 softmax + aggregation ----------------
__global__ __launch_bounds__(256) void agg_l1_csr(int E, int Ncnt)
{
    int b = blockIdx.y;
    int dst = (blockIdx.x * blockDim.x + threadIdx.x) >> 5;
    int lane = threadIdx.x & 31;
    if (dst >= Ncnt) return;
    const int* off  = g_off + b * (NN + 1);
    const int* srcv = g_esrc + b * ETOTM;
    const float* s1 = g_s1 + b * NN * 3;
    float* e0p = g_exp1 + (size_t)(b * 3 + 0) * ETOTM;
    float* e1p = g_exp1 + (size_t)(b * 3 + 1) * ETOTM;
    float* e2p = g_exp1 + (size_t)(b * 3 + 2) * ETOTM;

    int beg = off[dst], end = off[dst + 1];
    float dv0 = g_d1[b * NN * 3 + dst * 3 + 0];
    float dv1 = g_d1[b * NN * 3 + dst * 3 + 1];
    float dv2 = g_d1[b * NN * 3 + dst * 3 + 2];

    float den0 = 0.f, den1 = 0.f, den2 = 0.f;
    for (int i = beg + lane; i < end; i += 32) {
        int src = srcv[i];
        float e0 = s1[src * 3 + 0] + dv0;
        float e1 = s1[src * 3 + 1] + dv1;
        float e2 = s1[src * 3 + 2] + dv2;
        e0 = e0 > 0.f ? e0 : 0.2f * e0;
        e1 = e1 > 0.f ? e1 : 0.2f * e1;
        e2 = e2 > 0.f ? e2 : 0.2f * e2;
        float x0 = expf(e0), x1 = expf(e1), x2 = expf(e2);
        e0p[i] = x0; e1p[i] = x1; e2p[i] = x2;
        den0 += x0; den1 += x1; den2 += x2;
    }
    #pragma unroll
    for (int o = 16; o; o >>= 1) {
        den0 += __shfl_xor_sync(0xffffffffu, den0, o);
        den1 += __shfl_xor_sync(0xffffffffu, den1, o);
        den2 += __shfl_xor_sync(0xffffffffu, den2, o);
    }
    float r0 = 1.f / den0, r1 = 1.f / den1, r2 = 1.f / den2;
    if (lane == 0) {
        g_rden1[b * NN * 3 + dst * 3 + 0] = r0;
        g_rden1[b * NN * 3 + dst * 3 + 1] = r1;
        g_rden1[b * NN * 3 + dst * 3 + 2] = r2;
    }
    __syncwarp();

    float acc[12];
    #pragma unroll
    for (int k = 0; k < 12; k++) acc[k] = 0.f;
    const float4* h1b = (const float4*)(g_h1 + (size_t)b * NN * 384);

    #pragma unroll 2
    for (int i = beg; i < end; i++) {
        float a0 = e0p[i] * r0, a1 = e1p[i] * r1, a2 = e2p[i] * r2;
        int src = srcv[i];
        const float4* hs = h1b + (size_t)src * 96;
        float4 v0 = hs[lane];
        float4 v1 = hs[32 + lane];
        float4 v2 = hs[64 + lane];
        acc[0] += v0.x * a0; acc[1]  += v0.y * a0; acc[2]  += v0.z * a0; acc[3]  += v0.w * a0;
        acc[4] += v1.x * a1; acc[5]  += v1.y * a1; acc[6]  += v1.z * a1; acc[7]  += v1.w * a1;
        acc[8] += v2.x * a2; acc[9]  += v2.y * a2; acc[10] += v2.z * a2; acc[11] += v2.w * a2;
    }

    float4* og = (float4*)(g_agg1 + ((size_t)b * NN + dst) * 384);
    og[lane]      = make_float4(acc[0], acc[1], acc[2], acc[3]);
    og[32 + lane] = make_float4(acc[4], acc[5], acc[6], acc[7]);
    og[64 + lane] = make_float4(acc[8], acc[9], acc[10], acc[11]);
}

// ---------------- alpha output: edge-parallel, original order ----------------
__global__ void alpha_l1(const int* __restrict__ ei1, const int* __restrict__ ei2,
                         int E, int Ncnt, float* __restrict__ out, long long out_size)
{
    int t = blockIdx.x * blockDim.x + threadIdx.x;
    int Etot = E + Ncnt;
    if (t >= 2 * Etot) return;
    int b = (t >= Etot) ? 1 : 0;
    int e = t - b * Etot;
    const int* ei = b ? ei2 : ei1;
    int src, dst;
    if (e < E) { src = ei[e]; dst = ei[E + e]; }
    else       { src = e - E; dst = src; }
    src = min(max(src, 0), Ncnt - 1);
    dst = min(max(dst, 0), Ncnt - 1);

    const float* s1 = g_s1 + b * NN * 3;
    const float* d1 = g_d1 + b * NN * 3;
    const float* rd = g_rden1 + b * NN * 3;
    long long ob = 1 + (long long)b * Etot * 3 + 3LL * e;
    if (ob + 2 >= out_size) return;

    #pragma unroll
    for (int h = 0; h < 3; h++) {
        float v = s1[src * 3 + h] + d1[dst * 3 + h];
        v = v > 0.f ? v : 0.2f * v;
        out[ob + h] = expf(v) * rd[dst * 3 + h];
    }
}

// ---------------- layer-2 softmax + aggregation ----------------
__global__ __launch_bounds__(256) void agg_l2_csr(int E, int Ncnt)
{
    int b = blockIdx.y;
    int dst = (blockIdx.x * blockDim.x + threadIdx.x) >> 5;
    int lane = threadIdx.x & 31;
    if (dst >= Ncnt) return;
    const int* off  = g_off + b * (NN + 1);
    const int* srcv = g_esrc + b * ETOTM;
    const float* s2 = g_s2 + b * NN;
    float* xp = g_exp2 + (size_t)b * ETOTM;

    int beg = off[dst], end = off[dst + 1];
    float dv = g_d2[b * NN + dst];
    float den = 0.f;
    for (int i = beg + lane; i < end; i += 32) {
        int src = srcv[i];
        float e = s2[src] + dv;
        e = e > 0.f ? e : 0.2f * e;
        float x = expf(e);
        xp[i] = x;
        den += x;
    }
    #pragma unroll
    for (int o = 16; o; o >>= 1) den += __shfl_xor_sync(0xffffffffu, den, o);
    float r = 1.f / den;
    __syncwarp();

    float4 acc = make_float4(0.f, 0.f, 0.f, 0.f);
    const float4* h2b = (const float4*)(g_h2 + (size_t)b * NN * 128);
    #pragma unroll 2
    for (int i = beg; i < end; i++) {
        float a = xp[i] * r;
        int src = srcv[i];
        float4 v = h2b[(size_t)src * 32 + lane];
        acc.x += v.x * a; acc.y += v.y * a; acc.z += v.z * a; acc.w += v.w * a;
    }
    ((float4*)(g_agg2 + ((size_t)b * NN + dst) * 128))[lane] = acc;
}

// ---------------- pooling (node_attn == 1 identically) ----------------
__global__ void pool_kernel(const float* __restrict__ b2, int Ncnt)
{
    int c = blockIdx.x;
    int b = blockIdx.y;
    const float* ag = g_agg2 + (size_t)b * NN * 128;
    float bias = b2[c];
    float se = 0.f;
    for (int n = threadIdx.x; n < Ncnt; n += blockDim.x)
        se += ag[(size_t)n * 128 + c] + bias;
    __shared__ float r1[256];
    r1[threadIdx.x] = se;
    __syncthreads();
    for (int o = 128; o; o >>= 1) {
        if (threadIdx.x < o) r1[threadIdx.x] += r1[threadIdx.x + o];
        __syncthreads();
    }
    if (threadIdx.x == 0) {
        float m = r1[0] / (float)Ncnt;
        g_pool[b * 256 + c]       = m;
        g_pool[b * 256 + 128 + c] = m;
    }
}

// ---------------- cosine similarity ----------------
__global__ void sim_kernel(float* __restrict__ out, long long out_size)
{
    int t = threadIdx.x;
    float a = g_pool[t], b = g_pool[256 + t];
    __shared__ float sd_[256], sa[256], sb[256];
    sd_[t] = a * b; sa[t] = a * a; sb[t] = b * b;
    __syncthreads();
    for (int o = 128; o; o >>= 1) {
        if (t < o) { sd_[t] += sd_[t + o]; sa[t] += sa[t + o]; sb[t] += sb[t + o]; }
        __syncthreads();
    }
    if (t == 0 && out_size >= 1) {
        float n1 = fmaxf(sqrtf(sa[0]), 1e-8f);
        float n2 = fmaxf(sqrtf(sb[0]), 1e-8f);
        out[0] = sd_[0] / (n1 * n2);
    }
}

// ---------------- host launcher: fork-join overlap of CSR build with layer-1 --
extern "C" void kernel_launch(void* const* d_in, const int* in_sizes, int n_in,
                              void* d_out, int out_size)
{
    const float* x1  = (const float*)d_in[0];
    const int*   ei1 = (const int*)d_in[1];     // int32
    const float* x2  = (const float*)d_in[2];
    const int*   ei2 = (const int*)d_in[3];
    const float* W1  = (const float*)d_in[4];
    const float* as1 = (const float*)d_in[5];
    const float* ad1 = (const float*)d_in[6];
    const float* b1  = (const float*)d_in[7];
    const float* W2  = (const float*)d_in[8];
    const float* as2 = (const float*)d_in[9];
    const float* ad2 = (const float*)d_in[10];
    const float* b2  = (const float*)d_in[11];
    float* out = (float*)d_out;
    const long long osz = (long long)out_size;

    const int Ncnt = in_sizes[0] / 256;
    const int E    = in_sizes[1] / 2;
    const int Etot = E + Ncnt;

    const int e2blocks = (2 * Etot + 255) / 256;
    const int nwb = (Ncnt * 32 + 255) / 256;
    const int sdb = (2 * Ncnt * 32 + 255) / 256;

    static cudaStream_t s_side = nullptr;
    static cudaEvent_t s_fork = nullptr, s_join = nullptr;
    if (!s_side) {
        cudaStreamCreateWithFlags(&s_side, cudaStreamNonBlocking);
        cudaEventCreateWithFlags(&s_fork, cudaEventDisableTiming);
        cudaEventCreateWithFlags(&s_join, cudaEventDisableTiming);
    }

    // fork: CSR build on side stream; GEMM1 + sd chain on main stream
    cudaEventRecord(s_fork, 0);
    cudaStreamWaitEvent(s_side, s_fork, 0);

    init_deg<<<(2 * Ncnt + 255) / 256, 256, 0, s_side>>>(Ncnt);
    csr_count<<<e2blocks, 256, 0, s_side>>>(ei1, ei2, E, Ncnt);
    csr_scan<<<2, 1024, 0, s_side>>>(Ncnt, Etot);
    csr_scatter<<<e2blocks, 256, 0, s_side>>>(ei1, ei2, E, Ncnt);
    cudaEventRecord(s_join, s_side);

    prep_att<<<2, 768>>>(W1, as1, ad1, W2, as2, ad2);
    gemm_l1_tf32<<<dim3(3, (Ncnt + 127) / 128, 2), 256>>>(x1, x2, W1, Ncnt);
    sd1_x<<<sdb, 256>>>(x1, x2, Ncnt);

    // join: agg_l1 needs CSR + h1 + s1/d1
    cudaStreamWaitEvent(0, s_join, 0);
    agg_l1_csr<<<dim3(nwb, 2), 256>>>(E, Ncnt);
    alpha_l1<<<e2blocks, 256>>>(ei1, ei2, E, Ncnt, out, osz);

    // layer 2
    gemm_l2_tf32<<<dim3(1, (Ncnt + 127) / 128, 2), 256>>>(W2, b1, Ncnt);
    sd2_ag<<<sdb, 256>>>(b1, Ncnt);
    agg_l2_csr<<<dim3(nwb, 2), 256>>>(E, Ncnt);

    // pooling + similarity
    pool_kernel<<<dim3(128, 2), 256>>>(b2, Ncnt);
    sim_kernel<<<1, 256>>>(out, osz);
}